// round 17
// baseline (speedup 1.0000x reference)
#include <cuda_runtime.h>
#include <cuda_bf16.h>
#include <mma.h>
#include <math.h>
#include <stdint.h>

using namespace nvcuda;

// Problem constants: B=32, Cin=Cout=64, N=8192, modes=32
#define N_T    8192
#define N_ROWS 2048
#define N_F    32
#define N_J    64            // 2*modes, interleaved re/im
#define FWD_SPLITK 16
#define FWD_NCHUNK 8         // (8192/16)/64

// smem leading dims (bf16 elements). Multiples of 16 elements = 32 B so every row start
// keeps the 256-bit alignment wmma::load_matrix_sync requires.
#define A_LD   80            // 64 + 16 pad
#define BI_LD  144           // 128 + 16 pad
#define FWD_SMEM_BYTES ((2*128*A_LD + 2*64*A_LD) * 2)    // 61,440
#define INV_SMEM_BYTES ((2*128*A_LD + 2*64*BI_LD) * 2)   // 77,824

// ---------------- device scratch ----------------
__device__ __nv_bfloat16 g_tabF_hi[N_T * N_J];   // fwd table [t][j] bf16-hi (1 MB)
__device__ __nv_bfloat16 g_tabF_lo[N_T * N_J];   // residual
__device__ __nv_bfloat16 g_tabI_hi[N_J * N_T];   // inv table [j][t] bf16-hi (1 MB)
__device__ __nv_bfloat16 g_tabI_lo[N_J * N_T];
__device__ float2 g_cftA[160 * N_F];
__device__ int    g_cft_left[160];
__device__ int    g_cft_right[160];
__device__ float  g_cft_wl[160];
__device__ float  g_cft_wr[160];
__device__ float  g_Xpart[FWD_SPLITK * N_ROWS * N_J];  // 8 MB
__device__ float  g_Xc[N_ROWS * N_J];
__device__ float  g_gnorm[N_ROWS * N_F];
__device__ float  g_Gc[N_ROWS * N_J];

// float -> bf16 hi + residual lo, two at a time packed into u32
__device__ __forceinline__ void cvt2(float a, float b, uint32_t& hi, uint32_t& lo) {
  __nv_bfloat16 ah = __float2bfloat16(a), bh = __float2bfloat16(b);
  __nv_bfloat16 al = __float2bfloat16(a - __bfloat162float(ah));
  __nv_bfloat16 bl = __float2bfloat16(b - __bfloat162float(bh));
  hi = ((uint32_t)__bfloat16_as_ushort(bh) << 16) | (uint32_t)__bfloat16_as_ushort(ah);
  lo = ((uint32_t)__bfloat16_as_ushort(bl) << 16) | (uint32_t)__bfloat16_as_ushort(al);
}

// ---------------- setup: trig tables ----------------
// value(t,j): j even -> cos(2*pi*f*t/N), j odd -> +sin. Forward sign (-sin) is fixed in
// k_reduce_x; inverse sign is folded into g_Gc (imag stored as -alpha*ai).
__global__ void k_setup_tables() {
  int idx = blockIdx.x * blockDim.x + threadIdx.x;
  if (idx >= N_T * N_J) return;
  int t = idx >> 6, j = idx & 63, f = j >> 1;
  int r = (f * t) & (N_T - 1);
  float s, c;
  sincospif((float)r * (1.0f / 4096.0f), &s, &c);
  float val = (j & 1) ? s : c;
  __nv_bfloat16 h = __float2bfloat16(val);
  __nv_bfloat16 lo = __float2bfloat16(val - __bfloat162float(h));
  g_tabF_hi[t * N_J + j] = h;
  g_tabF_lo[t * N_J + j] = lo;
  g_tabI_hi[(size_t)j * N_T + t] = h;
  g_tabI_lo[(size_t)j * N_T + t] = lo;
}

// ---------------- setup: CFT combined weights (fp32, MUFU) ----------------
__global__ void k_setup_cft() {
  int e = blockIdx.x * blockDim.x + threadIdx.x;
  if (e < 160) {
    int l = e >> 3, m = e & 7;
    float cheb = -cospif((2.0f * m + 1.0f) / 16.0f);
    float ts = (float)l / 20.0f + 0.025f * (cheb + 1.0f);
    int right = (int)ceilf(ts * 8191.0f);
    if (right < 1) right = 1;
    while (right > 0 && (float)(right - 1) / 8191.0f >= ts) right--;
    while (right < 8191 && (float)right / 8191.0f < ts) right++;
    if (right > 8191) right = 8191;
    int left = right - 1; if (left < 0) left = 0;
    float tl = (float)left / 8191.0f;
    float tr = (float)right / 8191.0f;
    float den = (tr - tl == 0.0f) ? 1.0f : (tr - tl);
    float wr = (ts - tl) / den;
    g_cft_left[e] = left;  g_cft_right[e] = right;
    g_cft_wr[e] = wr;      g_cft_wl[e] = 1.0f - wr;
  }
  if (e >= 160 * 32) return;
  int p = e >> 5, f = e & 31;
  int l = p >> 3, kk = p & 7;
  float Wr = 0.0f, Wi = 0.0f;
#pragma unroll
  for (int mm = 0; mm < 8; mm++) {
    float q = (2.0f * mm + 1.0f) / 16.0f;
    float cheb = -cospif(q);
    float T = cospif((float)kk * (1.0f - q));
    float s, c;
    sincospif(cheb * (float)f * 0.05f, &s, &c);
    Wr += T * c;  Wi -= T * s;
  }
  Wr *= 0.025f; Wi *= 0.025f;
  float qphi = (float)((l * f) % 20) * 0.1f;
  float sn, cs;
  sincospif(qphi, &sn, &cs);
  g_cftA[e] = make_float2(Wr * cs + Wi * sn, -Wr * sn + Wi * cs);
}

// ---------------- kernel A: forward pruned DFT via WMMA bf16 3-split ----------------
// Xpart[sp][m][j] = sum_k x[m][k] * tabF[k][j]   (j odd carries +sin; sign fixed in reduce)
__global__ __launch_bounds__(256) void k_fwd_wmma(const float* __restrict__ x) {
  extern __shared__ __nv_bfloat16 sm[];
  __nv_bfloat16* Ahi = sm;                      // [128][A_LD]
  __nv_bfloat16* Alo = Ahi + 128 * A_LD;
  __nv_bfloat16* Bhi = Alo + 128 * A_LD;        // [64][A_LD]
  __nv_bfloat16* Blo = Bhi + 64 * A_LD;
  const int tid = threadIdx.x, wid = tid >> 5;
  const int m0 = blockIdx.x * 128;
  const int k0 = blockIdx.y * (N_T / FWD_SPLITK);

  wmma::fragment<wmma::accumulator, 16, 16, 16, float> acc[4];
#pragma unroll
  for (int n = 0; n < 4; n++) wmma::fill_fragment(acc[n], 0.0f);

  const int arow = tid >> 1, ahalf = tid & 1;           // A loader: half-row per thread
  const int brow = tid >> 2, bq = tid & 3;              // B loader: quarter-row per thread

  for (int c = 0; c < FWD_NCHUNK; c++) {
    __syncthreads();   // previous iter's fragment loads done before smem overwrite
    // A: x[m0+arow][k0+c*64 + ahalf*32 .. +31] -> bf16 hi/lo
    {
      const float4* src = (const float4*)(x + (size_t)(m0 + arow) * N_T + k0 + c * 64 + ahalf * 32);
      uint32_t* dh = (uint32_t*)(Ahi + arow * A_LD + ahalf * 32);
      uint32_t* dl = (uint32_t*)(Alo + arow * A_LD + ahalf * 32);
#pragma unroll
      for (int g = 0; g < 8; g++) {
        float4 v = src[g];
        uint32_t h01, l01, h23, l23;
        cvt2(v.x, v.y, h01, l01);
        cvt2(v.z, v.w, h23, l23);
        dh[g * 2] = h01; dh[g * 2 + 1] = h23;
        dl[g * 2] = l01; dl[g * 2 + 1] = l23;
      }
    }
    // B: tabF rows k0+c*64+brow, 16 cols per thread (2x uint4 hi + lo)
    {
      const size_t off = (size_t)(k0 + c * 64 + brow) * N_J + bq * 16;
      const uint4* sh = (const uint4*)(g_tabF_hi + off);
      const uint4* sl = (const uint4*)(g_tabF_lo + off);
      uint4* dh = (uint4*)(Bhi + brow * A_LD + bq * 16);
      uint4* dl = (uint4*)(Blo + brow * A_LD + bq * 16);
      dh[0] = sh[0]; dh[1] = sh[1];
      dl[0] = sl[0]; dl[1] = sl[1];
    }
    __syncthreads();
#pragma unroll
    for (int kt = 0; kt < 4; kt++) {
      wmma::fragment<wmma::matrix_a, 16, 16, 16, __nv_bfloat16, wmma::row_major> ah, al;
      wmma::load_matrix_sync(ah, Ahi + (wid * 16) * A_LD + kt * 16, A_LD);
      wmma::load_matrix_sync(al, Alo + (wid * 16) * A_LD + kt * 16, A_LD);
#pragma unroll
      for (int n = 0; n < 4; n++) {
        wmma::fragment<wmma::matrix_b, 16, 16, 16, __nv_bfloat16, wmma::row_major> bh, bl;
        wmma::load_matrix_sync(bh, Bhi + (kt * 16) * A_LD + n * 16, A_LD);
        wmma::load_matrix_sync(bl, Blo + (kt * 16) * A_LD + n * 16, A_LD);
        wmma::mma_sync(acc[n], ah, bh, acc[n]);
        wmma::mma_sync(acc[n], ah, bl, acc[n]);
        wmma::mma_sync(acc[n], al, bh, acc[n]);
      }
    }
  }
  float* outp = g_Xpart + ((size_t)blockIdx.y * N_ROWS + m0 + wid * 16) * N_J;
#pragma unroll
  for (int n = 0; n < 4; n++)
    wmma::store_matrix_sync(outp + n * 16, acc[n], N_J, wmma::mem_row_major);
}

// ---------------- split-K reduce + sign fix (j odd: +sin -> im = -sum) ----------------
__global__ void k_reduce_x() {
  int e = blockIdx.x * blockDim.x + threadIdx.x;
  if (e >= N_ROWS * N_J) return;
  float s = 0.0f;
#pragma unroll
  for (int i = 0; i < FWD_SPLITK; i++) s += g_Xpart[(size_t)i * N_ROWS * N_J + e];
  g_Xc[e] = (e & 1) ? -s : s;
}

// ---------------- kernel B: CFT magnitude + LayerNorm ----------------
__global__ __launch_bounds__(256) void k_cft_norm(const float* __restrict__ x,
                                                  const float* __restrict__ gamma,
                                                  const float* __restrict__ beta) {
  __shared__ float seg[8][160];
  int w = threadIdx.x >> 5, lane = threadIdx.x & 31;
  int m = blockIdx.x * 8 + w;
  const float* xr = x + (size_t)m * N_T;
  for (int p = lane; p < 160; p += 32)
    seg[w][p] = g_cft_wl[p] * xr[g_cft_left[p]] + g_cft_wr[p] * xr[g_cft_right[p]];
  __syncwarp();
  float re = 0.0f, im = 0.0f;
#pragma unroll 8
  for (int p = 0; p < 160; p++) {
    float s = seg[w][p];
    float2 A = g_cftA[p * 32 + lane];
    re += s * A.x;  im += s * A.y;
  }
  float mag = sqrtf(re * re + im * im);
  float mu = mag;
#pragma unroll
  for (int o = 16; o; o >>= 1) mu += __shfl_xor_sync(0xffffffffu, mu, o);
  mu *= (1.0f / 32.0f);
  float dd = mag - mu;
  float v = dd * dd;
#pragma unroll
  for (int o = 16; o; o >>= 1) v += __shfl_xor_sync(0xffffffffu, v, o);
  v *= (1.0f / 32.0f);
  g_gnorm[m * 32 + lane] = dd / sqrtf(v + 1e-5f) * gamma[lane] + beta[lane];
}

// ---------------- kernel C: sigmoid gate + complex channel mix ----------------
__global__ __launch_bounds__(256) void k_gate_mix(const float* __restrict__ w1r,
                                                  const float* __restrict__ w1i,
                                                  const float* __restrict__ gw) {
  __shared__ float sgn[64 * 32];
  __shared__ float sgw[64 * 64];
  __shared__ float sgr[64 * 32];
  __shared__ float sgi[64 * 32];
  int b = blockIdx.x, tid = threadIdx.x;
  for (int e = tid; e < 64 * 32; e += 256) sgn[e] = g_gnorm[b * 2048 + e];
  for (int e = tid; e < 64 * 64; e += 256) sgw[e] = gw[e];
  __syncthreads();
  for (int e = tid; e < 64 * 32; e += 256) {
    int o = e >> 5, f = e & 31;
    float s = 0.0f;
#pragma unroll 8
    for (int i = 0; i < 64; i++) s += sgw[o * 64 + i] * sgn[i * 32 + f];
    float gate = 1.0f / (1.0f + expf(-s));
    sgr[e] = g_Xc[(b * 64 + o) * 64 + 2 * f] * gate;
    sgi[e] = g_Xc[(b * 64 + o) * 64 + 2 * f + 1] * gate;
  }
  __syncthreads();
  for (int e = tid; e < 64 * 32; e += 256) {
    int o = e >> 5, f = e & 31;
    float ar = 0.0f, ai = 0.0f;
#pragma unroll 4
    for (int i = 0; i < 64; i++) {
      float wr = w1r[i * 2048 + o * 32 + f];
      float wi = w1i[i * 2048 + o * 32 + f];
      float gr = sgr[i * 32 + f];
      float gi = sgi[i * 32 + f];
      ar += gr * wr - gi * wi;
      ai += gr * wi + gi * wr;
    }
    float alpha = (f == 0 ? 1.0f : 2.0f) * (1.0f / 8192.0f);
    g_Gc[(b * 64 + o) * 64 + 2 * f]     =  alpha * ar;
    g_Gc[(b * 64 + o) * 64 + 2 * f + 1] = -alpha * ai;
  }
}

// ---------------- kernel D: inverse pruned DFT via WMMA bf16 3-split ----------------
// out[m][t] = sum_j Gc[m][j] * tabI[j][t];  K=64 resident, 128x128 output tile per CTA.
__global__ __launch_bounds__(256) void k_inv_wmma(float* __restrict__ out) {
  extern __shared__ __nv_bfloat16 sm[];
  __nv_bfloat16* Ahi = sm;                      // [128][A_LD]
  __nv_bfloat16* Alo = Ahi + 128 * A_LD;
  __nv_bfloat16* Bhi = Alo + 128 * A_LD;        // [64][BI_LD]
  __nv_bfloat16* Blo = Bhi + 64 * BI_LD;
  const int tid = threadIdx.x, wid = tid >> 5;
  const int m0 = blockIdx.y * 128;
  const int t0 = blockIdx.x * 128;

  // A: Gc rows (64 wide), half-row per thread
  {
    int arow = tid >> 1, ahalf = tid & 1;
    const float4* src = (const float4*)(g_Gc + (size_t)(m0 + arow) * N_J + ahalf * 32);
    uint32_t* dh = (uint32_t*)(Ahi + arow * A_LD + ahalf * 32);
    uint32_t* dl = (uint32_t*)(Alo + arow * A_LD + ahalf * 32);
#pragma unroll
    for (int g = 0; g < 8; g++) {
      float4 v = src[g];
      uint32_t h01, l01, h23, l23;
      cvt2(v.x, v.y, h01, l01);
      cvt2(v.z, v.w, h23, l23);
      dh[g * 2] = h01; dh[g * 2 + 1] = h23;
      dl[g * 2] = l01; dl[g * 2 + 1] = l23;
    }
  }
  // B: tabI rows j (stride 8192), 32 cols per thread (4x uint4 hi + lo)
  {
    int brow = tid >> 2, bq = tid & 3;
    const size_t off = (size_t)brow * N_T + t0 + bq * 32;
    const uint4* sh = (const uint4*)(g_tabI_hi + off);
    const uint4* sl = (const uint4*)(g_tabI_lo + off);
    uint4* dh = (uint4*)(Bhi + brow * BI_LD + bq * 32);
    uint4* dl = (uint4*)(Blo + brow * BI_LD + bq * 32);
#pragma unroll
    for (int g = 0; g < 4; g++) { dh[g] = sh[g]; dl[g] = sl[g]; }
  }
  __syncthreads();

  wmma::fragment<wmma::accumulator, 16, 16, 16, float> acc[8];
#pragma unroll
  for (int n = 0; n < 8; n++) wmma::fill_fragment(acc[n], 0.0f);
#pragma unroll
  for (int kt = 0; kt < 4; kt++) {
    wmma::fragment<wmma::matrix_a, 16, 16, 16, __nv_bfloat16, wmma::row_major> ah, al;
    wmma::load_matrix_sync(ah, Ahi + (wid * 16) * A_LD + kt * 16, A_LD);
    wmma::load_matrix_sync(al, Alo + (wid * 16) * A_LD + kt * 16, A_LD);
#pragma unroll
    for (int n = 0; n < 8; n++) {
      wmma::fragment<wmma::matrix_b, 16, 16, 16, __nv_bfloat16, wmma::row_major> bh, bl;
      wmma::load_matrix_sync(bh, Bhi + (kt * 16) * BI_LD + n * 16, BI_LD);
      wmma::load_matrix_sync(bl, Blo + (kt * 16) * BI_LD + n * 16, BI_LD);
      wmma::mma_sync(acc[n], ah, bh, acc[n]);
      wmma::mma_sync(acc[n], ah, bl, acc[n]);
      wmma::mma_sync(acc[n], al, bh, acc[n]);
    }
  }
  float* op = out + (size_t)(m0 + wid * 16) * N_T + t0;
#pragma unroll
  for (int n = 0; n < 8; n++)
    wmma::store_matrix_sync(op + n * 16, acc[n], N_T, wmma::mem_row_major);
}

// ---------------- launch ----------------
extern "C" void kernel_launch(void* const* d_in, const int* in_sizes, int n_in,
                              void* d_out, int out_size) {
  const float* x     = (const float*)d_in[0];
  const float* w1r   = (const float*)d_in[1];
  const float* w1i   = (const float*)d_in[2];
  const float* gw    = (const float*)d_in[3];
  const float* gamma = (const float*)d_in[4];
  const float* beta  = (const float*)d_in[5];
  float* out = (float*)d_out;

  // Unconditional (no static guards per harness rules); idempotent, not stream ops.
  cudaFuncSetAttribute(k_fwd_wmma, cudaFuncAttributeMaxDynamicSharedMemorySize, FWD_SMEM_BYTES);
  cudaFuncSetAttribute(k_inv_wmma, cudaFuncAttributeMaxDynamicSharedMemorySize, INV_SMEM_BYTES);

  k_setup_tables<<<(N_T * N_J + 255) / 256, 256>>>();
  k_setup_cft<<<20, 256>>>();
  k_fwd_wmma<<<dim3(N_ROWS / 128, FWD_SPLITK), 256, FWD_SMEM_BYTES>>>(x);
  k_reduce_x<<<(N_ROWS * N_J + 255) / 256, 256>>>();
  k_cft_norm<<<N_ROWS / 8, 256>>>(x, gamma, beta);
  k_gate_mix<<<32, 256>>>(w1r, w1i, gw);
  k_inv_wmma<<<dim3(N_T / 128, N_ROWS / 128), 256, INV_SMEM_BYTES>>>(out);
}